// round 5
// baseline (speedup 1.0000x reference)
#include <cuda_runtime.h>
#include <cuda_bf16.h>

#define N_NODES 100000
#define N_EDGES 600000
#define HID 128

typedef unsigned long long u64;

// Scratch (device globals: no allocation allowed in kernel_launch)
__device__ int   g_degi[N_NODES];
__device__ int   g_off[N_NODES];
__device__ int   g_end[N_NODES];
__device__ int   g_pos[N_NODES];
__device__ int   g_csr[N_EDGES];
__device__ int   g_cursor;
__device__ float g_dinv[N_NODES];

// ---------------------------------------------------------------------------
// K1: in-degree count (g_degi zeroed by cudaMemsetAsync)
// ---------------------------------------------------------------------------
__global__ void k_count(const int* __restrict__ dst) {
    int e = blockIdx.x * blockDim.x + threadIdx.x;
    if (e < N_EDGES) atomicAdd(&g_degi[dst[e]], 1);
}

// ---------------------------------------------------------------------------
// K2: slot allocation via warp-aggregated atomic cursor (CSR range order is
// irrelevant — only contiguity per node matters). Also writes dinv.
// ---------------------------------------------------------------------------
__global__ void k_alloc() {
    int i = blockIdx.x * blockDim.x + threadIdx.x;
    int lane = threadIdx.x & 31;
    bool valid = i < N_NODES;
    int d = valid ? g_degi[i] : 0;
    int sc = d;   // inclusive warp scan
    #pragma unroll
    for (int o = 1; o < 32; o <<= 1) {
        int u = __shfl_up_sync(~0u, sc, o);
        if (lane >= o) sc += u;
    }
    int total = __shfl_sync(~0u, sc, 31);
    int base = 0;
    if (lane == 31) base = atomicAdd(&g_cursor, total);
    base = __shfl_sync(~0u, base, 31);
    int off = base + sc - d;   // exclusive
    if (valid) {
        g_off[i] = off;
        g_pos[i] = off;
        g_end[i] = off + d;
        g_dinv[i] = rsqrtf((float)(1 + d));
    }
}

// ---------------------------------------------------------------------------
// K3: CSR fill
// ---------------------------------------------------------------------------
__global__ void k_fill(const int* __restrict__ src, const int* __restrict__ dst) {
    int e = blockIdx.x * blockDim.x + threadIdx.x;
    if (e < N_EDGES) {
        int p = atomicAdd(&g_pos[dst[e]], 1);
        g_csr[p] = src[e];
    }
}

// ---------------------------------------------------------------------------
// Packed f32x2 helpers (SASS FFMA2 — only reachable via PTX fma.rn.f32x2)
// ---------------------------------------------------------------------------
__device__ __forceinline__ u64 pack2(float v) {
    u64 r;
    asm("mov.b64 %0, {%1, %1};" : "=l"(r) : "f"(v));
    return r;
}
__device__ __forceinline__ void fma2(u64& d, u64 a, u64 b) {
    asm("fma.rn.f32x2 %0, %1, %2, %3;" : "=l"(d) : "l"(a), "l"(b), "l"(d));
}
__device__ __forceinline__ void unpack2(u64 v, float& lo, float& hi) {
    asm("mov.b64 {%0, %1}, %2;" : "=f"(lo), "=f"(hi) : "l"(v));
}

// ---------------------------------------------------------------------------
// Fused: gather(CSR, MLP-4) -> smem A -> GEMM(f32x2) -> bias/ReLU/res/LN
// Block 256 threads, tile 64 rows x 128 cols. smem: W 64KB + A^T 32KB.
// ---------------------------------------------------------------------------
__global__ void __launch_bounds__(256, 2)
k_fused(const float* __restrict__ W,
        const float* __restrict__ bias,
        const float* __restrict__ gamma,
        const float* __restrict__ beta,
        const float* __restrict__ x,
        float* __restrict__ out) {
    extern __shared__ float smf[];
    float* Ws = smf;               // [128][128] k-major
    float* As = smf + HID * HID;   // [128][64]  As[k*64+m]

    const float4* x4 = (const float4*)x;
    int tid = threadIdx.x;
    int lane = tid & 31, warp = tid >> 5;
    int rowBase = blockIdx.x * 64;

    // ---- Load W (64 KB)
    {
        const float4* W4 = (const float4*)W;
        float4* Ws4 = (float4*)Ws;
        #pragma unroll
        for (int i = tid; i < HID * HID / 4; i += 256) Ws4[i] = W4[i];
    }

    // ---- Gather: warp w handles rows w*8 .. w*8+7; lane owns float4 slice
    #pragma unroll
    for (int j = 0; j < 8; j++) {
        int m = warp * 8 + j;
        int node = rowBase + m;
        float4 acc = make_float4(0.f, 0.f, 0.f, 0.f);
        if (node < N_NODES) {
            float di = g_dinv[node];
            float4 v = x4[node * (HID / 4) + lane];
            float s2 = di * di;                       // self-loop norm
            acc.x = v.x * s2; acc.y = v.y * s2; acc.z = v.z * s2; acc.w = v.w * s2;
            int e = g_off[node], e1 = g_end[node];
            while (e < e1) {
                int cnt = min(e1 - e, 32);
                int s_l = (lane < cnt) ? g_csr[e + lane] : 0;
                float n_l = (lane < cnt) ? g_dinv[s_l] * di : 0.f;
                int cntR = (cnt + 3) & ~3;            // lanes >= cnt carry norm 0
                for (int q = 0; q < cntR; q += 4) {
                    int s0 = __shfl_sync(~0u, s_l, q + 0);
                    int s1 = __shfl_sync(~0u, s_l, q + 1);
                    int s2i = __shfl_sync(~0u, s_l, q + 2);
                    int s3 = __shfl_sync(~0u, s_l, q + 3);
                    float m0 = __shfl_sync(~0u, n_l, q + 0);
                    float m1 = __shfl_sync(~0u, n_l, q + 1);
                    float m2 = __shfl_sync(~0u, n_l, q + 2);
                    float m3 = __shfl_sync(~0u, n_l, q + 3);
                    // 4 independent loads in flight before any consumer
                    float4 v0 = x4[s0 * (HID / 4) + lane];
                    float4 v1 = x4[s1 * (HID / 4) + lane];
                    float4 v2 = x4[s2i * (HID / 4) + lane];
                    float4 v3 = x4[s3 * (HID / 4) + lane];
                    acc.x = fmaf(v0.x, m0, acc.x); acc.y = fmaf(v0.y, m0, acc.y);
                    acc.z = fmaf(v0.z, m0, acc.z); acc.w = fmaf(v0.w, m0, acc.w);
                    acc.x = fmaf(v1.x, m1, acc.x); acc.y = fmaf(v1.y, m1, acc.y);
                    acc.z = fmaf(v1.z, m1, acc.z); acc.w = fmaf(v1.w, m1, acc.w);
                    acc.x = fmaf(v2.x, m2, acc.x); acc.y = fmaf(v2.y, m2, acc.y);
                    acc.z = fmaf(v2.z, m2, acc.z); acc.w = fmaf(v2.w, m2, acc.w);
                    acc.x = fmaf(v3.x, m3, acc.x); acc.y = fmaf(v3.y, m3, acc.y);
                    acc.z = fmaf(v3.z, m3, acc.z); acc.w = fmaf(v3.w, m3, acc.w);
                }
                e += cnt;
            }
        }
        As[(lane * 4 + 0) * 64 + m] = acc.x;
        As[(lane * 4 + 1) * 64 + m] = acc.y;
        As[(lane * 4 + 2) * 64 + m] = acc.z;
        As[(lane * 4 + 3) * 64 + m] = acc.w;
    }
    __syncthreads();

    // ---- GEMM: micro-tile 4 rows x 8 cols, packed f32x2 accumulators
    int tn = tid & 15;   // cols tn*8 .. +7
    int tm = tid >> 4;   // rows tm*4 .. +3

    u64 acc2[4][4];
    #pragma unroll
    for (int i = 0; i < 4; i++)
        #pragma unroll
        for (int jj = 0; jj < 4; jj++) acc2[i][jj] = 0ull;

    #pragma unroll 4
    for (int k = 0; k < HID; k++) {
        float4 a = *(const float4*)&As[k * 64 + tm * 4];
        const u64* wrow = (const u64*)&Ws[k * HID + tn * 8];
        u64 b0 = wrow[0], b1 = wrow[1], b2 = wrow[2], b3 = wrow[3];
        u64 a0 = pack2(a.x), a1 = pack2(a.y), a2 = pack2(a.z), a3 = pack2(a.w);
        fma2(acc2[0][0], a0, b0); fma2(acc2[0][1], a0, b1);
        fma2(acc2[0][2], a0, b2); fma2(acc2[0][3], a0, b3);
        fma2(acc2[1][0], a1, b0); fma2(acc2[1][1], a1, b1);
        fma2(acc2[1][2], a1, b2); fma2(acc2[1][3], a1, b3);
        fma2(acc2[2][0], a2, b0); fma2(acc2[2][1], a2, b1);
        fma2(acc2[2][2], a2, b2); fma2(acc2[2][3], a2, b3);
        fma2(acc2[3][0], a3, b0); fma2(acc2[3][1], a3, b1);
        fma2(acc2[3][2], a3, b2); fma2(acc2[3][3], a3, b3);
    }

    // ---- Epilogue: bias, ReLU, residual, LayerNorm (16-lane shuffle reduce)
    int c0 = tn * 8;
    float bb[8], gg[8], be[8];
    {
        float4 t0 = *(const float4*)&bias[c0],  t1 = *(const float4*)&bias[c0 + 4];
        bb[0]=t0.x; bb[1]=t0.y; bb[2]=t0.z; bb[3]=t0.w; bb[4]=t1.x; bb[5]=t1.y; bb[6]=t1.z; bb[7]=t1.w;
        float4 g0 = *(const float4*)&gamma[c0], g1 = *(const float4*)&gamma[c0 + 4];
        gg[0]=g0.x; gg[1]=g0.y; gg[2]=g0.z; gg[3]=g0.w; gg[4]=g1.x; gg[5]=g1.y; gg[6]=g1.z; gg[7]=g1.w;
        float4 e0 = *(const float4*)&beta[c0],  e1 = *(const float4*)&beta[c0 + 4];
        be[0]=e0.x; be[1]=e0.y; be[2]=e0.z; be[3]=e0.w; be[4]=e1.x; be[5]=e1.y; be[6]=e1.z; be[7]=e1.w;
    }

    #pragma unroll
    for (int i = 0; i < 4; i++) {
        int row = rowBase + tm * 4 + i;
        bool valid = row < N_NODES;
        int rowc = valid ? row : 0;

        float av[8];
        #pragma unroll
        for (int jj = 0; jj < 4; jj++) unpack2(acc2[i][jj], av[2 * jj], av[2 * jj + 1]);

        const float4* xr = (const float4*)&x[(size_t)rowc * HID + c0];
        float4 x0 = xr[0], x1 = xr[1];
        float xv[8] = {x0.x, x0.y, x0.z, x0.w, x1.x, x1.y, x1.z, x1.w};

        float v[8];
        float sum = 0.f, sq = 0.f;
        #pragma unroll
        for (int j = 0; j < 8; j++) {
            float t = fmaxf(av[j] + bb[j], 0.f) + xv[j];
            v[j] = t;
            sum += t;
            sq  += t * t;
        }
        #pragma unroll
        for (int off = 8; off > 0; off >>= 1) {
            sum += __shfl_xor_sync(0xffffffffu, sum, off, 16);
            sq  += __shfl_xor_sync(0xffffffffu, sq,  off, 16);
        }
        float mu   = sum * (1.f / HID);
        float var  = sq * (1.f / HID) - mu * mu;
        float rstd = rsqrtf(var + 1e-8f);

        if (valid) {
            float o[8];
            #pragma unroll
            for (int j = 0; j < 8; j++)
                o[j] = (v[j] - mu) * rstd * gg[j] + be[j];
            float4* op = (float4*)&out[(size_t)row * HID + c0];
            op[0] = make_float4(o[0], o[1], o[2], o[3]);
            op[1] = make_float4(o[4], o[5], o[6], o[7]);
        }
    }
}

// ---------------------------------------------------------------------------
extern "C" void kernel_launch(void* const* d_in, const int* in_sizes, int n_in,
                              void* d_out, int out_size) {
    const float* x     = (const float*)d_in[0];
    const int*   ei    = (const int*)d_in[1];
    const float* W     = (const float*)d_in[2];
    const float* b     = (const float*)d_in[3];
    const float* gamma = (const float*)d_in[4];
    const float* beta  = (const float*)d_in[5];
    float* out = (float*)d_out;

    const int* src = ei;             // edge_index[0]
    const int* dst = ei + N_EDGES;   // edge_index[1]

    void* degi_ptr = nullptr;
    void* cursor_ptr = nullptr;
    cudaGetSymbolAddress(&degi_ptr, g_degi);
    cudaGetSymbolAddress(&cursor_ptr, g_cursor);
    cudaMemsetAsync(degi_ptr, 0, N_NODES * sizeof(int));
    cudaMemsetAsync(cursor_ptr, 0, sizeof(int));

    k_count<<<(N_EDGES + 255) / 256, 256>>>(dst);
    k_alloc<<<(N_NODES + 255) / 256, 256>>>();
    k_fill<<<(N_EDGES + 255) / 256, 256>>>(src, dst);

    int smem = (HID * HID + HID * 64) * sizeof(float);
    cudaFuncSetAttribute(k_fused, cudaFuncAttributeMaxDynamicSharedMemorySize, smem);
    k_fused<<<(N_NODES + 63) / 64, 256, smem>>>(W, b, gamma, beta, x, out);
}

// round 7
// speedup vs baseline: 1.3326x; 1.3326x over previous
#include <cuda_runtime.h>
#include <cuda_bf16.h>

#define N_NODES 100000
#define N_EDGES 600000
#define HID 128
#define TILE_M 128
#define NBLK ((N_NODES + TILE_M - 1) / TILE_M)   // 782

typedef unsigned long long u64;

// Scratch (device globals: no allocation allowed in kernel_launch)
__device__ int   g_degi[N_NODES];
__device__ int   g_off[N_NODES];
__device__ int   g_end[N_NODES];
__device__ int   g_pos[N_NODES];
__device__ int   g_csr[N_EDGES];
__device__ int   g_cursor;
__device__ float g_dinv[N_NODES];

// ---------------------------------------------------------------------------
// K1: in-degree count (g_degi starts zeroed: static init first run, k_fill after)
// ---------------------------------------------------------------------------
__global__ void k_count(const int* __restrict__ dst) {
    int e = blockIdx.x * blockDim.x + threadIdx.x;
    if (e < N_EDGES) atomicAdd(&g_degi[dst[e]], 1);
}

// ---------------------------------------------------------------------------
// K2: slot allocation via warp-aggregated atomic cursor; writes dinv.
// ---------------------------------------------------------------------------
__global__ void k_alloc() {
    int i = blockIdx.x * blockDim.x + threadIdx.x;
    int lane = threadIdx.x & 31;
    bool valid = i < N_NODES;
    int d = valid ? g_degi[i] : 0;
    int sc = d;   // inclusive warp scan
    #pragma unroll
    for (int o = 1; o < 32; o <<= 1) {
        int u = __shfl_up_sync(~0u, sc, o);
        if (lane >= o) sc += u;
    }
    int total = __shfl_sync(~0u, sc, 31);
    int base = 0;
    if (lane == 31) base = atomicAdd(&g_cursor, total);
    base = __shfl_sync(~0u, base, 31);
    int off = base + sc - d;   // exclusive
    if (valid) {
        g_off[i] = off;
        g_pos[i] = off;
        g_end[i] = off + d;
        g_dinv[i] = rsqrtf((float)(1 + d));
    }
}

// ---------------------------------------------------------------------------
// K3: CSR fill; also resets g_degi / g_cursor for the next graph replay
// ---------------------------------------------------------------------------
__global__ void k_fill(const int* __restrict__ src, const int* __restrict__ dst) {
    int e = blockIdx.x * blockDim.x + threadIdx.x;
    if (e < N_EDGES) {
        int p = atomicAdd(&g_pos[dst[e]], 1);
        g_csr[p] = src[e];
    }
    if (e < N_NODES) g_degi[e] = 0;
    if (e == 0) g_cursor = 0;
}

// ---------------------------------------------------------------------------
// Packed f32x2 helpers
// ---------------------------------------------------------------------------
__device__ __forceinline__ u64 pack2(float v) {
    u64 r;
    asm("mov.b64 %0, {%1, %1};" : "=l"(r) : "f"(v));
    return r;
}
__device__ __forceinline__ void fma2(u64& d, u64 a, u64 b) {
    asm("fma.rn.f32x2 %0, %1, %2, %3;" : "=l"(d) : "l"(a), "l"(b), "l"(d));
}
__device__ __forceinline__ void unpack2(u64 v, float& lo, float& hi) {
    asm("mov.b64 {%0, %1}, %2;" : "=f"(lo), "=f"(hi) : "l"(v));
}

// As swizzled index (floats): row k, col m. Keeps 4-aligned groups contiguous.
__device__ __forceinline__ int aidx(int k, int m) {
    return k * 128 + (m ^ ((k & 31) * 4));
}

// ---------------------------------------------------------------------------
// Fused kernel: gather(CSR) -> As -> 2-pass GEMM(f32x2) -> bias/ReLU/res/LN
// Tile 128 rows x 128 cols, 256 threads, 8x8 micro-tile (two 64-col passes).
// smem: Ws [128][64] = 32KB, As [128][128] = 64KB. 2 CTAs/SM.
// ---------------------------------------------------------------------------
__global__ void __launch_bounds__(256, 2)
k_fused(const float* __restrict__ W,
        const float* __restrict__ bias,
        const float* __restrict__ gamma,
        const float* __restrict__ beta,
        const float* __restrict__ x,
        float* __restrict__ out) {
    extern __shared__ float smf[];
    float* Ws = smf;                 // [128][64] k-major
    float* As = smf + 128 * 64;      // [128][128] swizzled

    int tid = threadIdx.x;
    int lane = tid & 31, warp = tid >> 5;
    int rowBase = blockIdx.x * TILE_M;

    // ---- Load W cols 0..63 (pass 1)
    {
        const float4* W4 = (const float4*)W;
        float4* Ws4 = (float4*)Ws;
        #pragma unroll
        for (int i = tid; i < 128 * 16; i += 256) {
            int r = i >> 4, c4 = i & 15;
            Ws4[i] = W4[r * 32 + c4];
        }
    }

    // ---- Gather: warp w rows w*16..w*16+15. Lane owns k = lane + 32c.
    for (int jj = 0; jj < 16; jj++) {
        int m = warp * 16 + jj;
        int node = rowBase + m;
        float acc[4] = {0.f, 0.f, 0.f, 0.f};
        if (node < N_NODES) {
            float di = g_dinv[node];
            float s2 = di * di;
            #pragma unroll
            for (int c = 0; c < 4; c++)
                acc[c] = x[node * HID + c * 32 + lane] * s2;
            int e = g_off[node], e1 = g_end[node];
            while (e < e1) {
                int cnt = min(e1 - e, 32);
                int s_l = (lane < cnt) ? g_csr[e + lane] : 0;
                float n_l = (lane < cnt) ? g_dinv[s_l] * di : 0.f;
                int cntR = (cnt + 7) & ~7;     // padded lanes carry norm 0
                for (int q = 0; q < cntR; q += 8) {
                    int sidx[8]; float snm[8];
                    #pragma unroll
                    for (int t = 0; t < 8; t++) {
                        sidx[t] = __shfl_sync(~0u, s_l, q + t);
                        snm[t]  = __shfl_sync(~0u, n_l, q + t);
                    }
                    #pragma unroll
                    for (int c = 0; c < 4; c++) {
                        float v[8];
                        #pragma unroll
                        for (int t = 0; t < 8; t++)
                            v[t] = x[sidx[t] * HID + c * 32 + lane];
                        #pragma unroll
                        for (int t = 0; t < 8; t++)
                            acc[c] = fmaf(v[t], snm[t], acc[c]);
                    }
                }
                e += cnt;
            }
        }
        #pragma unroll
        for (int c = 0; c < 4; c++)
            As[aidx(lane + 32 * c, m)] = acc[c];
    }
    __syncthreads();

    // ---- GEMM thread layout: 16x16 grid; rows tm*8..+7, cols tn*4..+3 (+pass)
    int tn = tid & 15;
    int tm = tid >> 4;
    int mA = tm * 8;

    u64 accA[4][4], accB[4][4];    // [row-pair][col], pass 1 / pass 2
    #pragma unroll
    for (int i = 0; i < 4; i++)
        #pragma unroll
        for (int j = 0; j < 4; j++) { accA[i][j] = 0ull; accB[i][j] = 0ull; }

    // ---- Pass 1 (cols 0..63)
    #pragma unroll 8
    for (int k = 0; k < HID; k++) {
        int swz = (k & 31) * 4;
        const float* ar = &As[k * 128];
        ulonglong2 a01 = *(const ulonglong2*)&ar[mA ^ swz];        // rows (0,1),(2,3)
        ulonglong2 a23 = *(const ulonglong2*)&ar[(mA + 4) ^ swz];  // rows (4,5),(6,7)
        float4 wv = *(const float4*)&Ws[k * 64 + tn * 4];
        u64 w0 = pack2(wv.x), w1 = pack2(wv.y), w2 = pack2(wv.z), w3 = pack2(wv.w);
        fma2(accA[0][0], a01.x, w0); fma2(accA[0][1], a01.x, w1);
        fma2(accA[0][2], a01.x, w2); fma2(accA[0][3], a01.x, w3);
        fma2(accA[1][0], a01.y, w0); fma2(accA[1][1], a01.y, w1);
        fma2(accA[1][2], a01.y, w2); fma2(accA[1][3], a01.y, w3);
        fma2(accA[2][0], a23.x, w0); fma2(accA[2][1], a23.x, w1);
        fma2(accA[2][2], a23.x, w2); fma2(accA[2][3], a23.x, w3);
        fma2(accA[3][0], a23.y, w0); fma2(accA[3][1], a23.y, w1);
        fma2(accA[3][2], a23.y, w2); fma2(accA[3][3], a23.y, w3);
    }

    // ---- Reload W cols 64..127
    __syncthreads();
    {
        const float4* W4 = (const float4*)W;
        float4* Ws4 = (float4*)Ws;
        #pragma unroll
        for (int i = tid; i < 128 * 16; i += 256) {
            int r = i >> 4, c4 = i & 15;
            Ws4[i] = W4[r * 32 + 16 + c4];
        }
    }
    __syncthreads();

    // ---- Pass 2 (cols 64..127)
    #pragma unroll 8
    for (int k = 0; k < HID; k++) {
        int swz = (k & 31) * 4;
        const float* ar = &As[k * 128];
        ulonglong2 a01 = *(const ulonglong2*)&ar[mA ^ swz];
        ulonglong2 a23 = *(const ulonglong2*)&ar[(mA + 4) ^ swz];
        float4 wv = *(const float4*)&Ws[k * 64 + tn * 4];
        u64 w0 = pack2(wv.x), w1 = pack2(wv.y), w2 = pack2(wv.z), w3 = pack2(wv.w);
        fma2(accB[0][0], a01.x, w0); fma2(accB[0][1], a01.x, w1);
        fma2(accB[0][2], a01.x, w2); fma2(accB[0][3], a01.x, w3);
        fma2(accB[1][0], a01.y, w0); fma2(accB[1][1], a01.y, w1);
        fma2(accB[1][2], a01.y, w2); fma2(accB[1][3], a01.y, w3);
        fma2(accB[2][0], a23.x, w0); fma2(accB[2][1], a23.x, w1);
        fma2(accB[2][2], a23.x, w2); fma2(accB[2][3], a23.x, w3);
        fma2(accB[3][0], a23.y, w0); fma2(accB[3][1], a23.y, w1);
        fma2(accB[3][2], a23.y, w2); fma2(accB[3][3], a23.y, w3);
    }

    // ---- Epilogue: bias, ReLU, residual, LayerNorm (16-lane shuffle reduce)
    int c0 = tn * 4;
    float bb[8], gg[8], be[8];
    {
        float4 t0 = *(const float4*)&bias[c0],  t1 = *(const float4*)&bias[64 + c0];
        bb[0]=t0.x; bb[1]=t0.y; bb[2]=t0.z; bb[3]=t0.w; bb[4]=t1.x; bb[5]=t1.y; bb[6]=t1.z; bb[7]=t1.w;
        float4 g0 = *(const float4*)&gamma[c0], g1 = *(const float4*)&gamma[64 + c0];
        gg[0]=g0.x; gg[1]=g0.y; gg[2]=g0.z; gg[3]=g0.w; gg[4]=g1.x; gg[5]=g1.y; gg[6]=g1.z; gg[7]=g1.w;
        float4 e0 = *(const float4*)&beta[c0],  e1 = *(const float4*)&beta[64 + c0];
        be[0]=e0.x; be[1]=e0.y; be[2]=e0.z; be[3]=e0.w; be[4]=e1.x; be[5]=e1.y; be[6]=e1.z; be[7]=e1.w;
    }

    #pragma unroll
    for (int rp = 0; rp < 4; rp++) {
        float lo[8], hi[8];
        #pragma unroll
        for (int c = 0; c < 4; c++) {
            unpack2(accA[rp][c], lo[c], hi[c]);
            unpack2(accB[rp][c], lo[4 + c], hi[4 + c]);
        }
        #pragma unroll
        for (int half = 0; half < 2; half++) {
            float* av = half ? hi : lo;
            int row = rowBase + tm * 8 + rp * 2 + half;
            bool valid = row < N_NODES;
            int rowc = valid ? row : 0;

            float4 x0 = *(const float4*)&x[(size_t)rowc * HID + c0];
            float4 x1 = *(const float4*)&x[(size_t)rowc * HID + 64 + c0];
            float xv[8] = {x0.x, x0.y, x0.z, x0.w, x1.x, x1.y, x1.z, x1.w};

            float v[8];
            float sum = 0.f, sq = 0.f;
            #pragma unroll
            for (int j = 0; j < 8; j++) {
                float t = fmaxf(av[j] + bb[j], 0.f) + xv[j];
                v[j] = t;
                sum += t;
                sq  += t * t;
            }
            #pragma unroll
            for (int off = 8; off > 0; off >>= 1) {
                sum += __shfl_xor_sync(0xffffffffu, sum, off, 16);
                sq  += __shfl_xor_sync(0xffffffffu, sq,  off, 16);
            }
            float mu   = sum * (1.f / HID);
            float var  = sq * (1.f / HID) - mu * mu;
            float rstd = rsqrtf(var + 1e-8f);

            if (valid) {
                float o[8];
                #pragma unroll
                for (int j = 0; j < 8; j++)
                    o[j] = (v[j] - mu) * rstd * gg[j] + be[j];
                float4* op0 = (float4*)&out[(size_t)row * HID + c0];
                float4* op1 = (float4*)&out[(size_t)row * HID + 64 + c0];
                *op0 = make_float4(o[0], o[1], o[2], o[3]);
                *op1 = make_float4(o[4], o[5], o[6], o[7]);
            }
        }
    }
}

// ---------------------------------------------------------------------------
extern "C" void kernel_launch(void* const* d_in, const int* in_sizes, int n_in,
                              void* d_out, int out_size) {
    const float* x     = (const float*)d_in[0];
    const int*   ei    = (const int*)d_in[1];
    const float* W     = (const float*)d_in[2];
    const float* b     = (const float*)d_in[3];
    const float* gamma = (const float*)d_in[4];
    const float* beta  = (const float*)d_in[5];
    float* out = (float*)d_out;

    const int* src = ei;             // edge_index[0]
    const int* dst = ei + N_EDGES;   // edge_index[1]

    k_count<<<(N_EDGES + 255) / 256, 256>>>(dst);
    k_alloc<<<(N_NODES + 255) / 256, 256>>>();
    k_fill<<<(N_EDGES + 255) / 256, 256>>>(src, dst);

    int smem = (128 * 64 + 128 * 128) * sizeof(float);   // 96 KB
    cudaFuncSetAttribute(k_fused, cudaFuncAttributeMaxDynamicSharedMemorySize, smem);
    k_fused<<<NBLK, 256, smem>>>(W, b, gamma, beta, x, out);
}

// round 8
// speedup vs baseline: 1.3341x; 1.0011x over previous
#include <cuda_runtime.h>
#include <cuda_bf16.h>

#define N_NODES 100000
#define N_EDGES 600000
#define HID 128
#define TILE_M 128
#define NBLK ((N_NODES + TILE_M - 1) / TILE_M)   // 782

typedef unsigned long long u64;

// Scratch (device globals: no allocation allowed in kernel_launch)
__device__ int   g_degi[N_NODES];
__device__ int   g_off[N_NODES];
__device__ int   g_end[N_NODES];
__device__ int   g_pos[N_NODES];
__device__ int   g_csr[N_EDGES];
__device__ int   g_cursor;
__device__ float g_dinv[N_NODES];

// ---------------------------------------------------------------------------
// K1: in-degree count (g_degi starts zeroed: static init first run, k_fill after)
// ---------------------------------------------------------------------------
__global__ void k_count(const int* __restrict__ dst) {
    int e = blockIdx.x * blockDim.x + threadIdx.x;
    if (e < N_EDGES) atomicAdd(&g_degi[dst[e]], 1);
}

// ---------------------------------------------------------------------------
// K2: slot allocation via warp-aggregated atomic cursor; writes dinv.
// ---------------------------------------------------------------------------
__global__ void k_alloc() {
    int i = blockIdx.x * blockDim.x + threadIdx.x;
    int lane = threadIdx.x & 31;
    bool valid = i < N_NODES;
    int d = valid ? g_degi[i] : 0;
    int sc = d;   // inclusive warp scan
    #pragma unroll
    for (int o = 1; o < 32; o <<= 1) {
        int u = __shfl_up_sync(~0u, sc, o);
        if (lane >= o) sc += u;
    }
    int total = __shfl_sync(~0u, sc, 31);
    int base = 0;
    if (lane == 31) base = atomicAdd(&g_cursor, total);
    base = __shfl_sync(~0u, base, 31);
    int off = base + sc - d;   // exclusive
    if (valid) {
        g_off[i] = off;
        g_pos[i] = off;
        g_end[i] = off + d;
        g_dinv[i] = rsqrtf((float)(1 + d));
    }
}

// ---------------------------------------------------------------------------
// K3: CSR fill; also resets g_degi / g_cursor for the next graph replay
// ---------------------------------------------------------------------------
__global__ void k_fill(const int* __restrict__ src, const int* __restrict__ dst) {
    int e = blockIdx.x * blockDim.x + threadIdx.x;
    if (e < N_EDGES) {
        int p = atomicAdd(&g_pos[dst[e]], 1);
        g_csr[p] = src[e];
    }
    if (e < N_NODES) g_degi[e] = 0;
    if (e == 0) g_cursor = 0;
}

// ---------------------------------------------------------------------------
// Packed f32x2 helpers
// ---------------------------------------------------------------------------
__device__ __forceinline__ u64 pack2(float v) {
    u64 r;
    asm("mov.b64 %0, {%1, %1};" : "=l"(r) : "f"(v));
    return r;
}
__device__ __forceinline__ void fma2(u64& d, u64 a, u64 b) {
    asm("fma.rn.f32x2 %0, %1, %2, %3;" : "=l"(d) : "l"(a), "l"(b), "l"(d));
}
__device__ __forceinline__ void unpack2(u64 v, float& lo, float& hi) {
    asm("mov.b64 {%0, %1}, %2;" : "=f"(lo), "=f"(hi) : "l"(v));
}

// As swizzled index (floats): row k, col m. Keeps 4-aligned groups contiguous.
__device__ __forceinline__ int aidx(int k, int m) {
    return k * 128 + (m ^ ((k & 31) * 4));
}

// ---------------------------------------------------------------------------
// Fused kernel: gather(CSR) -> As -> 2-pass GEMM(f32x2) -> bias/ReLU/res/LN
// Tile 128 rows x 128 cols, 256 threads, 8x8 micro-tile (two 64-col passes).
// smem: Ws [128][64] = 32KB, As [128][128] = 64KB. 2 CTAs/SM.
// ---------------------------------------------------------------------------
__global__ void __launch_bounds__(256, 2)
k_fused(const float* __restrict__ W,
        const float* __restrict__ bias,
        const float* __restrict__ gamma,
        const float* __restrict__ beta,
        const float* __restrict__ x,
        float* __restrict__ out) {
    extern __shared__ float smf[];
    float* Ws = smf;                 // [128][64] k-major
    float* As = smf + 128 * 64;      // [128][128] swizzled

    int tid = threadIdx.x;
    int lane = tid & 31, warp = tid >> 5;
    int rowBase = blockIdx.x * TILE_M;

    // ---- Load W cols 0..63 (pass 1)
    {
        const float4* W4 = (const float4*)W;
        float4* Ws4 = (float4*)Ws;
        #pragma unroll
        for (int i = tid; i < 128 * 16; i += 256) {
            int r = i >> 4, c4 = i & 15;
            Ws4[i] = W4[r * 32 + c4];
        }
    }

    // ---- Gather: warp w rows w*16..w*16+15. Lane owns k = lane + 32c.
    for (int jj = 0; jj < 16; jj++) {
        int m = warp * 16 + jj;
        int node = rowBase + m;
        float acc[4] = {0.f, 0.f, 0.f, 0.f};
        if (node < N_NODES) {
            float di = g_dinv[node];
            float s2 = di * di;
            #pragma unroll
            for (int c = 0; c < 4; c++)
                acc[c] = x[node * HID + c * 32 + lane] * s2;
            int e = g_off[node], e1 = g_end[node];
            while (e < e1) {
                int cnt = min(e1 - e, 32);
                int s_l = (lane < cnt) ? g_csr[e + lane] : 0;
                float n_l = (lane < cnt) ? g_dinv[s_l] * di : 0.f;
                int cntR = (cnt + 7) & ~7;     // padded lanes carry norm 0
                for (int q = 0; q < cntR; q += 8) {
                    int sidx[8]; float snm[8];
                    #pragma unroll
                    for (int t = 0; t < 8; t++) {
                        sidx[t] = __shfl_sync(~0u, s_l, q + t);
                        snm[t]  = __shfl_sync(~0u, n_l, q + t);
                    }
                    #pragma unroll
                    for (int c = 0; c < 4; c++) {
                        float v[8];
                        #pragma unroll
                        for (int t = 0; t < 8; t++)
                            v[t] = x[sidx[t] * HID + c * 32 + lane];
                        #pragma unroll
                        for (int t = 0; t < 8; t++)
                            acc[c] = fmaf(v[t], snm[t], acc[c]);
                    }
                }
                e += cnt;
            }
        }
        #pragma unroll
        for (int c = 0; c < 4; c++)
            As[aidx(lane + 32 * c, m)] = acc[c];
    }
    __syncthreads();

    // ---- GEMM thread layout: 16x16 grid; rows tm*8..+7, cols tn*4..+3 (+pass)
    int tn = tid & 15;
    int tm = tid >> 4;
    int mA = tm * 8;

    u64 accA[4][4], accB[4][4];    // [row-pair][col], pass 1 / pass 2
    #pragma unroll
    for (int i = 0; i < 4; i++)
        #pragma unroll
        for (int j = 0; j < 4; j++) { accA[i][j] = 0ull; accB[i][j] = 0ull; }

    // ---- Pass 1 (cols 0..63)
    #pragma unroll 8
    for (int k = 0; k < HID; k++) {
        int swz = (k & 31) * 4;
        const float* ar = &As[k * 128];
        ulonglong2 a01 = *(const ulonglong2*)&ar[mA ^ swz];        // rows (0,1),(2,3)
        ulonglong2 a23 = *(const ulonglong2*)&ar[(mA + 4) ^ swz];  // rows (4,5),(6,7)
        float4 wv = *(const float4*)&Ws[k * 64 + tn * 4];
        u64 w0 = pack2(wv.x), w1 = pack2(wv.y), w2 = pack2(wv.z), w3 = pack2(wv.w);
        fma2(accA[0][0], a01.x, w0); fma2(accA[0][1], a01.x, w1);
        fma2(accA[0][2], a01.x, w2); fma2(accA[0][3], a01.x, w3);
        fma2(accA[1][0], a01.y, w0); fma2(accA[1][1], a01.y, w1);
        fma2(accA[1][2], a01.y, w2); fma2(accA[1][3], a01.y, w3);
        fma2(accA[2][0], a23.x, w0); fma2(accA[2][1], a23.x, w1);
        fma2(accA[2][2], a23.x, w2); fma2(accA[2][3], a23.x, w3);
        fma2(accA[3][0], a23.y, w0); fma2(accA[3][1], a23.y, w1);
        fma2(accA[3][2], a23.y, w2); fma2(accA[3][3], a23.y, w3);
    }

    // ---- Reload W cols 64..127
    __syncthreads();
    {
        const float4* W4 = (const float4*)W;
        float4* Ws4 = (float4*)Ws;
        #pragma unroll
        for (int i = tid; i < 128 * 16; i += 256) {
            int r = i >> 4, c4 = i & 15;
            Ws4[i] = W4[r * 32 + 16 + c4];
        }
    }
    __syncthreads();

    // ---- Pass 2 (cols 64..127)
    #pragma unroll 8
    for (int k = 0; k < HID; k++) {
        int swz = (k & 31) * 4;
        const float* ar = &As[k * 128];
        ulonglong2 a01 = *(const ulonglong2*)&ar[mA ^ swz];
        ulonglong2 a23 = *(const ulonglong2*)&ar[(mA + 4) ^ swz];
        float4 wv = *(const float4*)&Ws[k * 64 + tn * 4];
        u64 w0 = pack2(wv.x), w1 = pack2(wv.y), w2 = pack2(wv.z), w3 = pack2(wv.w);
        fma2(accB[0][0], a01.x, w0); fma2(accB[0][1], a01.x, w1);
        fma2(accB[0][2], a01.x, w2); fma2(accB[0][3], a01.x, w3);
        fma2(accB[1][0], a01.y, w0); fma2(accB[1][1], a01.y, w1);
        fma2(accB[1][2], a01.y, w2); fma2(accB[1][3], a01.y, w3);
        fma2(accB[2][0], a23.x, w0); fma2(accB[2][1], a23.x, w1);
        fma2(accB[2][2], a23.x, w2); fma2(accB[2][3], a23.x, w3);
        fma2(accB[3][0], a23.y, w0); fma2(accB[3][1], a23.y, w1);
        fma2(accB[3][2], a23.y, w2); fma2(accB[3][3], a23.y, w3);
    }

    // ---- Epilogue: bias, ReLU, residual, LayerNorm (16-lane shuffle reduce)
    int c0 = tn * 4;
    float bb[8], gg[8], be[8];
    {
        float4 t0 = *(const float4*)&bias[c0],  t1 = *(const float4*)&bias[64 + c0];
        bb[0]=t0.x; bb[1]=t0.y; bb[2]=t0.z; bb[3]=t0.w; bb[4]=t1.x; bb[5]=t1.y; bb[6]=t1.z; bb[7]=t1.w;
        float4 g0 = *(const float4*)&gamma[c0], g1 = *(const float4*)&gamma[64 + c0];
        gg[0]=g0.x; gg[1]=g0.y; gg[2]=g0.z; gg[3]=g0.w; gg[4]=g1.x; gg[5]=g1.y; gg[6]=g1.z; gg[7]=g1.w;
        float4 e0 = *(const float4*)&beta[c0],  e1 = *(const float4*)&beta[64 + c0];
        be[0]=e0.x; be[1]=e0.y; be[2]=e0.z; be[3]=e0.w; be[4]=e1.x; be[5]=e1.y; be[6]=e1.z; be[7]=e1.w;
    }

    #pragma unroll
    for (int rp = 0; rp < 4; rp++) {
        float lo[8], hi[8];
        #pragma unroll
        for (int c = 0; c < 4; c++) {
            unpack2(accA[rp][c], lo[c], hi[c]);
            unpack2(accB[rp][c], lo[4 + c], hi[4 + c]);
        }
        #pragma unroll
        for (int half = 0; half < 2; half++) {
            float* av = half ? hi : lo;
            int row = rowBase + tm * 8 + rp * 2 + half;
            bool valid = row < N_NODES;
            int rowc = valid ? row : 0;

            float4 x0 = *(const float4*)&x[(size_t)rowc * HID + c0];
            float4 x1 = *(const float4*)&x[(size_t)rowc * HID + 64 + c0];
            float xv[8] = {x0.x, x0.y, x0.z, x0.w, x1.x, x1.y, x1.z, x1.w};

            float v[8];
            float sum = 0.f, sq = 0.f;
            #pragma unroll
            for (int j = 0; j < 8; j++) {
                float t = fmaxf(av[j] + bb[j], 0.f) + xv[j];
                v[j] = t;
                sum += t;
                sq  += t * t;
            }
            #pragma unroll
            for (int off = 8; off > 0; off >>= 1) {
                sum += __shfl_xor_sync(0xffffffffu, sum, off, 16);
                sq  += __shfl_xor_sync(0xffffffffu, sq,  off, 16);
            }
            float mu   = sum * (1.f / HID);
            float var  = sq * (1.f / HID) - mu * mu;
            float rstd = rsqrtf(var + 1e-8f);

            if (valid) {
                float o[8];
                #pragma unroll
                for (int j = 0; j < 8; j++)
                    o[j] = (v[j] - mu) * rstd * gg[j] + be[j];
                float4* op0 = (float4*)&out[(size_t)row * HID + c0];
                float4* op1 = (float4*)&out[(size_t)row * HID + 64 + c0];
                *op0 = make_float4(o[0], o[1], o[2], o[3]);
                *op1 = make_float4(o[4], o[5], o[6], o[7]);
            }
        }
    }
}

// ---------------------------------------------------------------------------
extern "C" void kernel_launch(void* const* d_in, const int* in_sizes, int n_in,
                              void* d_out, int out_size) {
    const float* x     = (const float*)d_in[0];
    const int*   ei    = (const int*)d_in[1];
    const float* W     = (const float*)d_in[2];
    const float* b     = (const float*)d_in[3];
    const float* gamma = (const float*)d_in[4];
    const float* beta  = (const float*)d_in[5];
    float* out = (float*)d_out;

    const int* src = ei;             // edge_index[0]
    const int* dst = ei + N_EDGES;   // edge_index[1]

    k_count<<<(N_EDGES + 255) / 256, 256>>>(dst);
    k_alloc<<<(N_NODES + 255) / 256, 256>>>();
    k_fill<<<(N_EDGES + 255) / 256, 256>>>(src, dst);

    int smem = (128 * 64 + 128 * 128) * sizeof(float);   // 96 KB
    cudaFuncSetAttribute(k_fused, cudaFuncAttributeMaxDynamicSharedMemorySize, smem);
    k_fused<<<NBLK, 256, smem>>>(W, b, gamma, beta, x, out);
}